// round 15
// baseline (speedup 1.0000x reference)
#include <cuda_runtime.h>

typedef unsigned long long u64;

#define HID 10

struct Params {
    const float* W[9];
    const float* b[9];
};

// Weight bank layout: weights duplicated into (w,w) float2 so one constant
// load feeds a packed-across-points f32x2 FMA.
struct __align__(16) CW {
    float2 Wh[7][HID][HID];   // layers 2..8 (10 -> 10), duplicated
    float2 bh2[7][HID];       // (b, b) pre-packed (both points share bias)
    float2 W1[2][HID];        // layer 1 (2 -> 10), duplicated
    float2 W9[HID];           // layer 9 (10 -> 1), duplicated
    float2 b9_2;              // (b9, b9)
    float  b1[HID];
    float  b9;
};

__constant__ CW c_s;          // read path: constant port (no LDS, no GPR staging)
__device__ CW g_stage;        // staging buffer filled by prep_kernel
__device__ unsigned int g_vb_counter;

__device__ __forceinline__ u64 pk2(float lo, float hi) {
    u64 r; asm("mov.b64 %0,{%1,%2};" : "=l"(r) : "f"(lo), "f"(hi)); return r;
}
__device__ __forceinline__ void upk2(u64 v, float& lo, float& hi) {
    asm("mov.b64 {%0,%1},%2;" : "=f"(lo), "=f"(hi) : "l"(v));
}
__device__ __forceinline__ u64 fma2(u64 a, u64 b, u64 c) {
    u64 d; asm("fma.rn.f32x2 %0,%1,%2,%3;" : "=l"(d) : "l"(a), "l"(b), "l"(c)); return d;
}
__device__ __forceinline__ u64 mul2(u64 a, u64 b) {
    u64 d; asm("mul.rn.f32x2 %0,%1,%2;" : "=l"(d) : "l"(a), "l"(b)); return d;
}

// Single-instruction MUFU tanh (sm_90+): 1 op, ~16 cyc, no fma-pipe cost.
__device__ __forceinline__ float tanh_fast(float z) {
    float t;
    asm("tanh.approx.f32 %0, %1;" : "=f"(t) : "f"(z));
    return t;
}

// Prep: pack duplicated weight layout into g_stage and reset the counter.
__global__ void prep_kernel(Params p) {
    int t = threadIdx.x;
    if (t == 0) g_vb_counter = 0;
    for (int l = 0; l < 7; l++)
        for (int i = t; i < HID * HID; i += blockDim.x) {
            float w = p.W[l + 1][i];
            g_stage.Wh[l][i / HID][i % HID] = make_float2(w, w);
        }
    for (int l = 0; l < 7; l++)
        for (int i = t; i < HID; i += blockDim.x) {
            float b = p.b[l + 1][i];
            g_stage.bh2[l][i] = make_float2(b, b);
        }
    for (int i = t; i < 2 * HID; i += blockDim.x) {
        float w = p.W[0][i];
        g_stage.W1[i / HID][i % HID] = make_float2(w, w);
    }
    for (int i = t; i < HID; i += blockDim.x) {
        float w = p.W[8][i];
        g_stage.W9[i] = make_float2(w, w);
    }
    for (int i = t; i < HID; i += blockDim.x) g_stage.b1[i] = p.b[0][i];
    if (t == 0) {
        float b9 = p.b[8][0];
        g_stage.b9   = b9;
        g_stage.b9_2 = make_float2(b9, b9);
    }
}

// ---------------------------------------------------------------------------
// Persistent fused kernel with dynamic work-stealing over virtual blocks.
// Weights come from __constant__ memory (constant port; zero smem traffic).
//   vb in [0, nfBlocks): jet path, 2 points/thread, across-point f32x2
//     packing of all four jet components (T, X, Tt, XX). Hidden-layer loop
//     FULLY UNROLLED so ptxas can pipeline LDCU across layer boundaries.
//   vb in [nfBlocks, totalVB): forward-only path, 128 points per vb.
// ---------------------------------------------------------------------------
__global__ void __launch_bounds__(128, 3)
fused_kernel(const float* __restrict__ Xf,
             const float* __restrict__ p0, const float* __restrict__ p1,
             const float* __restrict__ p2,
             float* __restrict__ out,
             int nf, int n0, int nb)
{
    __shared__ int s_vb;

    const int nfBlocks = (nf + 255) >> 8;
    const int total    = n0 + 2 * nb;
    const int totalVB  = nfBlocks + ((total + 127) >> 7);

    const u64 ONE  = pk2(1.0f, 1.0f);
    const u64 NEG1 = pk2(-1.0f, -1.0f);
    const u64 NEG2 = pk2(-2.0f, -2.0f);

    for (;;) {
        if (threadIdx.x == 0)
            s_vb = (int)atomicAdd(&g_vb_counter, 1u);
        __syncthreads();
        int vb = s_vb;
        if (vb >= totalVB) break;
        __syncthreads();   // protect s_vb before next overwrite

        if (vb >= nfBlocks) {
            // ---------------- forward-only path ----------------
            int i = (vb - nfBlocks) * 128 + threadIdx.x;
            if (i >= total) continue;

            const float* src;
            int loc, off;
            if (i < n0)           { src = p0; loc = i;           off = nf; }
            else if (i < n0 + nb) { src = p1; loc = i - n0;      off = nf + n0; }
            else                  { src = p2; loc = i - n0 - nb; off = nf + n0 + nb; }

            float x  = src[2 * loc + 0];
            float tt = src[2 * loc + 1];

            float h[HID];
            #pragma unroll
            for (int j = 0; j < HID; j++)
                h[j] = tanh_fast(fmaf(x, c_s.W1[0][j].x, fmaf(tt, c_s.W1[1][j].x, c_s.b1[j])));

            #pragma unroll 1
            for (int l = 0; l < 7; l++) {
                float z[HID];
                #pragma unroll
                for (int j = 0; j < HID; j++) z[j] = c_s.bh2[l][j].x;
                #pragma unroll
                for (int k = 0; k < HID; k++) {
                    float hk = h[k];
                    #pragma unroll
                    for (int j = 0; j < HID; j++)
                        z[j] = fmaf(hk, c_s.Wh[l][k][j].x, z[j]);
                }
                #pragma unroll
                for (int j = 0; j < HID; j++) h[j] = tanh_fast(z[j]);
            }

            float u = c_s.b9;
            #pragma unroll
            for (int k = 0; k < HID; k++) u = fmaf(h[k], c_s.W9[k].x, u);

            out[off + loc] = u;
            continue;
        }

        // ---------------- jet path: 2 points per thread ----------------
        int i0 = vb * 256 + threadIdx.x;
        int i1 = i0 + 128;
        int c0 = min(i0, nf - 1);
        int c1 = min(i1, nf - 1);

        float2 xy0 = reinterpret_cast<const float2*>(Xf)[c0];
        float2 xy1 = reinterpret_cast<const float2*>(Xf)[c1];

        // Packed-across-points jet state.
        u64 T[HID], X[HID], Tt[HID], XX[HID];

        // Layer 1: z = w0*x + w1*t + b; zx = w0, zt = w1, zxx = 0.
        #pragma unroll
        for (int j = 0; j < HID; j++) {
            float w0 = c_s.W1[0][j].x;
            float w1 = c_s.W1[1][j].x;
            float b  = c_s.b1[j];
            float z0 = fmaf(xy0.x, w0, fmaf(xy0.y, w1, b));
            float z1 = fmaf(xy1.x, w0, fmaf(xy1.y, w1, b));
            u64 Tn  = pk2(tanh_fast(z0), tanh_fast(z1));
            u64 T2  = mul2(Tn, Tn);
            u64 SV  = fma2(T2, NEG1, ONE);              // 1 - t^2
            u64 W0d = *reinterpret_cast<const u64*>(&c_s.W1[0][j]);
            u64 W1d = *reinterpret_cast<const u64*>(&c_s.W1[1][j]);
            u64 W02 = mul2(W0d, W0d);                   // zx^2
            u64 G   = mul2(Tn, W02);
            u64 H   = mul2(G, NEG2);                    // -2 t zx^2  (zxx=0)
            T[j]  = Tn;
            X[j]  = mul2(SV, W0d);
            Tt[j] = mul2(SV, W1d);
            XX[j] = mul2(SV, H);
        }

        // Hidden layers 2..8 — FULLY UNROLLED for cross-layer LDCU pipelining.
        #pragma unroll
        for (int l = 0; l < 7; l++) {
            u64 Z[HID], ZX[HID], ZT[HID], ZXX[HID];
            #pragma unroll
            for (int j = 0; j < HID; j++) {
                Z[j]   = *reinterpret_cast<const u64*>(&c_s.bh2[l][j]);  // (b,b)
                ZX[j]  = 0ull;
                ZT[j]  = 0ull;
                ZXX[j] = 0ull;
            }
            #pragma unroll
            for (int k = 0; k < HID; k++) {
                u64 Tk = T[k], Xk = X[k], Ttk = Tt[k], XXk = XX[k];
                #pragma unroll
                for (int j = 0; j < HID; j++) {
                    u64 w = *reinterpret_cast<const u64*>(&c_s.Wh[l][k][j]);
                    Z[j]   = fma2(Tk,  w, Z[j]);
                    ZX[j]  = fma2(Xk,  w, ZX[j]);
                    ZT[j]  = fma2(Ttk, w, ZT[j]);
                    ZXX[j] = fma2(XXk, w, ZXX[j]);
                }
            }
            #pragma unroll
            for (int j = 0; j < HID; j++) {
                float z0, z1;  upk2(Z[j], z0, z1);
                u64 Tn  = pk2(tanh_fast(z0), tanh_fast(z1));
                u64 T2  = mul2(Tn, Tn);
                u64 SV  = fma2(T2, NEG1, ONE);          // 1 - t^2
                u64 ZX2 = mul2(ZX[j], ZX[j]);
                u64 G   = mul2(Tn, ZX2);
                u64 H   = fma2(G, NEG2, ZXX[j]);        // zxx - 2 t zx^2
                T[j]  = Tn;
                XX[j] = mul2(SV, H);
                X[j]  = mul2(SV, ZX[j]);
                Tt[j] = mul2(SV, ZT[j]);
            }
        }

        // Output layer (10 -> 1), linear; fully packed.
        u64 U   = *reinterpret_cast<const u64*>(&c_s.b9_2);
        u64 UX  = 0ull, UT = 0ull, UXX = 0ull;
        #pragma unroll
        for (int k = 0; k < HID; k++) {
            u64 w = *reinterpret_cast<const u64*>(&c_s.W9[k]);
            U   = fma2(T[k],  w, U);
            UX  = fma2(X[k],  w, UX);
            UT  = fma2(Tt[k], w, UT);
            UXX = fma2(XX[k], w, UXX);
        }

        const float nu = 0.0031830988618379067f;   // 0.01 / pi
        u64 NEGNU = pk2(-nu, -nu);
        u64 F = fma2(U, UX, fma2(NEGNU, UXX, UT)); // u_t + u*u_x - nu*u_xx

        float u0, u1;     upk2(U, u0, u1);
        float ux0, ux1;   upk2(UX, ux0, ux1);
        float uxx0, uxx1; upk2(UXX, uxx0, uxx1);
        float f0, f1;     upk2(F, f0, f1);

        int offF = nf + n0 + 2 * nb;
        if (i0 < nf) {
            out[i0]               = u0;
            out[offF + i0]        = f0;
            out[offF + nf + i0]   = ux0;
            out[offF + 2*nf + i0] = uxx0;
        }
        if (i1 < nf) {
            out[i1]               = u1;
            out[offF + i1]        = f1;
            out[offF + nf + i1]   = ux1;
            out[offF + 2*nf + i1] = uxx1;
        }
    }
}

// ---------------------------------------------------------------------------
// Output layout (reference tuple order, concatenated):
//   [0, nf) u_pred_f | [nf, +n0) u_pred_0 | [+nb) left | [+nb) right
//   | [+nf) f | [+nf) u_x | [+nf) u_xx
// ---------------------------------------------------------------------------
extern "C" void kernel_launch(void* const* d_in, const int* in_sizes, int n_in,
                              void* d_out, int out_size)
{
    Params p;
    for (int i = 0; i < 9; i++) {
        p.W[i] = (const float*)d_in[4 + 2 * i];
        p.b[i] = (const float*)d_in[5 + 2 * i];
    }
    const float* Xf = (const float*)d_in[0];
    const float* x0 = (const float*)d_in[1];
    const float* xl = (const float*)d_in[2];
    const float* xr = (const float*)d_in[3];

    int nf = in_sizes[0] / 2;
    int n0 = in_sizes[1] / 2;
    int nb = in_sizes[2] / 2;

    float* out = (float*)d_out;

    int nfBlocks  = (nf + 255) / 256;
    int fwdBlocks = (n0 + 2 * nb + 127) / 128;
    int totalVB   = nfBlocks + fwdBlocks;

    // One full wave: 152 SMs (GB300) x 3 blocks/SM.
    int grid = 152 * 3;
    if (grid > totalVB) grid = totalVB;

    // 1) pack weights into staging + reset counter, 2) D2D copy into the
    //    constant bank (graph-capturable memcpy node), 3) main kernel.
    prep_kernel<<<1, 128>>>(p);
    void* stage_ptr = nullptr;
    cudaGetSymbolAddress(&stage_ptr, g_stage);
    cudaMemcpyToSymbolAsync(c_s, stage_ptr, sizeof(CW), 0,
                            cudaMemcpyDeviceToDevice, 0);
    fused_kernel<<<grid, 128>>>(Xf, x0, xl, xr, out, nf, n0, nb);
}

// round 16
// speedup vs baseline: 1.0865x; 1.0865x over previous
#include <cuda_runtime.h>

typedef unsigned long long u64;

#define HID 10

struct Params {
    const float* W[9];
    const float* b[9];
};

// Weight bank layout: weights duplicated into (w,w) float2 so one constant
// load feeds a packed-across-points f32x2 FMA.
struct __align__(16) CW {
    float2 Wh[7][HID][HID];   // layers 2..8 (10 -> 10), duplicated
    float2 bh2[7][HID];       // (b, b) pre-packed (both points share bias)
    float2 W1[2][HID];        // layer 1 (2 -> 10), duplicated
    float2 W9[HID];           // layer 9 (10 -> 1), duplicated
    float2 b9_2;              // (b9, b9)
    float  b1[HID];
    float  b9;
};

__constant__ CW c_s;          // read path: constant port (no LDS, no GPR staging)
__device__ CW g_stage;        // staging buffer filled by prep_kernel
__device__ unsigned int g_vb_counter;

__device__ __forceinline__ u64 pk2(float lo, float hi) {
    u64 r; asm("mov.b64 %0,{%1,%2};" : "=l"(r) : "f"(lo), "f"(hi)); return r;
}
__device__ __forceinline__ void upk2(u64 v, float& lo, float& hi) {
    asm("mov.b64 {%0,%1},%2;" : "=f"(lo), "=f"(hi) : "l"(v));
}
__device__ __forceinline__ u64 fma2(u64 a, u64 b, u64 c) {
    u64 d; asm("fma.rn.f32x2 %0,%1,%2,%3;" : "=l"(d) : "l"(a), "l"(b), "l"(c)); return d;
}
__device__ __forceinline__ u64 mul2(u64 a, u64 b) {
    u64 d; asm("mul.rn.f32x2 %0,%1,%2;" : "=l"(d) : "l"(a), "l"(b)); return d;
}

// Single-instruction MUFU tanh (sm_90+): 1 op, ~16 cyc, no fma-pipe cost.
__device__ __forceinline__ float tanh_fast(float z) {
    float t;
    asm("tanh.approx.f32 %0, %1;" : "=f"(t) : "f"(z));
    return t;
}

// Prep: pack duplicated weight layout into g_stage and reset the counter.
__global__ void prep_kernel(Params p) {
    int t = threadIdx.x;
    if (t == 0) g_vb_counter = 0;
    for (int l = 0; l < 7; l++)
        for (int i = t; i < HID * HID; i += blockDim.x) {
            float w = p.W[l + 1][i];
            g_stage.Wh[l][i / HID][i % HID] = make_float2(w, w);
        }
    for (int l = 0; l < 7; l++)
        for (int i = t; i < HID; i += blockDim.x) {
            float b = p.b[l + 1][i];
            g_stage.bh2[l][i] = make_float2(b, b);
        }
    for (int i = t; i < 2 * HID; i += blockDim.x) {
        float w = p.W[0][i];
        g_stage.W1[i / HID][i % HID] = make_float2(w, w);
    }
    for (int i = t; i < HID; i += blockDim.x) {
        float w = p.W[8][i];
        g_stage.W9[i] = make_float2(w, w);
    }
    for (int i = t; i < HID; i += blockDim.x) g_stage.b1[i] = p.b[0][i];
    if (t == 0) {
        float b9 = p.b[8][0];
        g_stage.b9   = b9;
        g_stage.b9_2 = make_float2(b9, b9);
    }
}

// ---------------------------------------------------------------------------
// Persistent fused kernel with dynamic work-stealing over virtual blocks.
// Weights come from __constant__ memory (constant port; zero smem traffic).
//   vb in [0, nfBlocks): jet path, 2 points/thread, across-point f32x2
//     packing of all four jet components (T, X, Tt, XX). Hidden-layer loop
//     unrolled x2 (body ~16KB: fits L1.5 I$, enables cross-layer LDCU
//     pipelining — full unroll at 56KB thrashed I$, rolled gives none).
//   vb in [nfBlocks, totalVB): forward-only path, 128 points per vb.
// ---------------------------------------------------------------------------
__global__ void __launch_bounds__(128, 3)
fused_kernel(const float* __restrict__ Xf,
             const float* __restrict__ p0, const float* __restrict__ p1,
             const float* __restrict__ p2,
             float* __restrict__ out,
             int nf, int n0, int nb)
{
    __shared__ int s_vb;

    const int nfBlocks = (nf + 255) >> 8;
    const int total    = n0 + 2 * nb;
    const int totalVB  = nfBlocks + ((total + 127) >> 7);

    const u64 ONE  = pk2(1.0f, 1.0f);
    const u64 NEG1 = pk2(-1.0f, -1.0f);
    const u64 NEG2 = pk2(-2.0f, -2.0f);

    for (;;) {
        if (threadIdx.x == 0)
            s_vb = (int)atomicAdd(&g_vb_counter, 1u);
        __syncthreads();
        int vb = s_vb;
        if (vb >= totalVB) break;
        __syncthreads();   // protect s_vb before next overwrite

        if (vb >= nfBlocks) {
            // ---------------- forward-only path ----------------
            int i = (vb - nfBlocks) * 128 + threadIdx.x;
            if (i >= total) continue;

            const float* src;
            int loc, off;
            if (i < n0)           { src = p0; loc = i;           off = nf; }
            else if (i < n0 + nb) { src = p1; loc = i - n0;      off = nf + n0; }
            else                  { src = p2; loc = i - n0 - nb; off = nf + n0 + nb; }

            float x  = src[2 * loc + 0];
            float tt = src[2 * loc + 1];

            float h[HID];
            #pragma unroll
            for (int j = 0; j < HID; j++)
                h[j] = tanh_fast(fmaf(x, c_s.W1[0][j].x, fmaf(tt, c_s.W1[1][j].x, c_s.b1[j])));

            #pragma unroll 1
            for (int l = 0; l < 7; l++) {
                float z[HID];
                #pragma unroll
                for (int j = 0; j < HID; j++) z[j] = c_s.bh2[l][j].x;
                #pragma unroll
                for (int k = 0; k < HID; k++) {
                    float hk = h[k];
                    #pragma unroll
                    for (int j = 0; j < HID; j++)
                        z[j] = fmaf(hk, c_s.Wh[l][k][j].x, z[j]);
                }
                #pragma unroll
                for (int j = 0; j < HID; j++) h[j] = tanh_fast(z[j]);
            }

            float u = c_s.b9;
            #pragma unroll
            for (int k = 0; k < HID; k++) u = fmaf(h[k], c_s.W9[k].x, u);

            out[off + loc] = u;
            continue;
        }

        // ---------------- jet path: 2 points per thread ----------------
        int i0 = vb * 256 + threadIdx.x;
        int i1 = i0 + 128;
        int c0 = min(i0, nf - 1);
        int c1 = min(i1, nf - 1);

        float2 xy0 = reinterpret_cast<const float2*>(Xf)[c0];
        float2 xy1 = reinterpret_cast<const float2*>(Xf)[c1];

        // Packed-across-points jet state.
        u64 T[HID], X[HID], Tt[HID], XX[HID];

        // Layer 1: z = w0*x + w1*t + b; zx = w0, zt = w1, zxx = 0.
        #pragma unroll
        for (int j = 0; j < HID; j++) {
            float w0 = c_s.W1[0][j].x;
            float w1 = c_s.W1[1][j].x;
            float b  = c_s.b1[j];
            float z0 = fmaf(xy0.x, w0, fmaf(xy0.y, w1, b));
            float z1 = fmaf(xy1.x, w0, fmaf(xy1.y, w1, b));
            u64 Tn  = pk2(tanh_fast(z0), tanh_fast(z1));
            u64 T2  = mul2(Tn, Tn);
            u64 SV  = fma2(T2, NEG1, ONE);              // 1 - t^2
            u64 W0d = *reinterpret_cast<const u64*>(&c_s.W1[0][j]);
            u64 W1d = *reinterpret_cast<const u64*>(&c_s.W1[1][j]);
            u64 W02 = mul2(W0d, W0d);                   // zx^2
            u64 G   = mul2(Tn, W02);
            u64 H   = mul2(G, NEG2);                    // -2 t zx^2  (zxx=0)
            T[j]  = Tn;
            X[j]  = mul2(SV, W0d);
            Tt[j] = mul2(SV, W1d);
            XX[j] = mul2(SV, H);
        }

        // Hidden layers 2..8 — unroll x2: body fits L1.5 I$, allows ptxas to
        // overlap next-layer constant loads with this layer's activations.
        #pragma unroll 2
        for (int l = 0; l < 7; l++) {
            u64 Z[HID], ZX[HID], ZT[HID], ZXX[HID];
            #pragma unroll
            for (int j = 0; j < HID; j++) {
                Z[j]   = *reinterpret_cast<const u64*>(&c_s.bh2[l][j]);  // (b,b)
                ZX[j]  = 0ull;
                ZT[j]  = 0ull;
                ZXX[j] = 0ull;
            }
            #pragma unroll
            for (int k = 0; k < HID; k++) {
                u64 Tk = T[k], Xk = X[k], Ttk = Tt[k], XXk = XX[k];
                #pragma unroll
                for (int j = 0; j < HID; j++) {
                    u64 w = *reinterpret_cast<const u64*>(&c_s.Wh[l][k][j]);
                    Z[j]   = fma2(Tk,  w, Z[j]);
                    ZX[j]  = fma2(Xk,  w, ZX[j]);
                    ZT[j]  = fma2(Ttk, w, ZT[j]);
                    ZXX[j] = fma2(XXk, w, ZXX[j]);
                }
            }
            #pragma unroll
            for (int j = 0; j < HID; j++) {
                float z0, z1;  upk2(Z[j], z0, z1);
                u64 Tn  = pk2(tanh_fast(z0), tanh_fast(z1));
                u64 T2  = mul2(Tn, Tn);
                u64 SV  = fma2(T2, NEG1, ONE);          // 1 - t^2
                u64 ZX2 = mul2(ZX[j], ZX[j]);
                u64 G   = mul2(Tn, ZX2);
                u64 H   = fma2(G, NEG2, ZXX[j]);        // zxx - 2 t zx^2
                T[j]  = Tn;
                XX[j] = mul2(SV, H);
                X[j]  = mul2(SV, ZX[j]);
                Tt[j] = mul2(SV, ZT[j]);
            }
        }

        // Output layer (10 -> 1), linear; fully packed.
        u64 U   = *reinterpret_cast<const u64*>(&c_s.b9_2);
        u64 UX  = 0ull, UT = 0ull, UXX = 0ull;
        #pragma unroll
        for (int k = 0; k < HID; k++) {
            u64 w = *reinterpret_cast<const u64*>(&c_s.W9[k]);
            U   = fma2(T[k],  w, U);
            UX  = fma2(X[k],  w, UX);
            UT  = fma2(Tt[k], w, UT);
            UXX = fma2(XX[k], w, UXX);
        }

        const float nu = 0.0031830988618379067f;   // 0.01 / pi
        u64 NEGNU = pk2(-nu, -nu);
        u64 F = fma2(U, UX, fma2(NEGNU, UXX, UT)); // u_t + u*u_x - nu*u_xx

        float u0, u1;     upk2(U, u0, u1);
        float ux0, ux1;   upk2(UX, ux0, ux1);
        float uxx0, uxx1; upk2(UXX, uxx0, uxx1);
        float f0, f1;     upk2(F, f0, f1);

        int offF = nf + n0 + 2 * nb;
        if (i0 < nf) {
            out[i0]               = u0;
            out[offF + i0]        = f0;
            out[offF + nf + i0]   = ux0;
            out[offF + 2*nf + i0] = uxx0;
        }
        if (i1 < nf) {
            out[i1]               = u1;
            out[offF + i1]        = f1;
            out[offF + nf + i1]   = ux1;
            out[offF + 2*nf + i1] = uxx1;
        }
    }
}

// ---------------------------------------------------------------------------
// Output layout (reference tuple order, concatenated):
//   [0, nf) u_pred_f | [nf, +n0) u_pred_0 | [+nb) left | [+nb) right
//   | [+nf) f | [+nf) u_x | [+nf) u_xx
// ---------------------------------------------------------------------------
extern "C" void kernel_launch(void* const* d_in, const int* in_sizes, int n_in,
                              void* d_out, int out_size)
{
    Params p;
    for (int i = 0; i < 9; i++) {
        p.W[i] = (const float*)d_in[4 + 2 * i];
        p.b[i] = (const float*)d_in[5 + 2 * i];
    }
    const float* Xf = (const float*)d_in[0];
    const float* x0 = (const float*)d_in[1];
    const float* xl = (const float*)d_in[2];
    const float* xr = (const float*)d_in[3];

    int nf = in_sizes[0] / 2;
    int n0 = in_sizes[1] / 2;
    int nb = in_sizes[2] / 2;

    float* out = (float*)d_out;

    int nfBlocks  = (nf + 255) / 256;
    int fwdBlocks = (n0 + 2 * nb + 127) / 128;
    int totalVB   = nfBlocks + fwdBlocks;

    // One full wave: 152 SMs (GB300) x 3 blocks/SM.
    int grid = 152 * 3;
    if (grid > totalVB) grid = totalVB;

    // 1) pack weights into staging + reset counter, 2) D2D copy into the
    //    constant bank (graph-capturable memcpy node), 3) main kernel.
    prep_kernel<<<1, 128>>>(p);
    void* stage_ptr = nullptr;
    cudaGetSymbolAddress(&stage_ptr, g_stage);
    cudaMemcpyToSymbolAsync(c_s, stage_ptr, sizeof(CW), 0,
                            cudaMemcpyDeviceToDevice, 0);
    fused_kernel<<<grid, 128>>>(Xf, x0, xl, xr, out, nf, n0, nb);
}